// round 2
// baseline (speedup 1.0000x reference)
#include <cuda_runtime.h>

#define N_NODES 8192
#define F_IN    128
#define F_OUTD  64
#define ALPHA   0.2f
#define BI      32
#define BJ      128

// Scratch (allocations are forbidden; use __device__ globals)
__device__ float g_wh[N_NODES * F_OUTD];
__device__ float g_src[N_NODES];
__device__ float g_dst[N_NODES];

// ---------------------------------------------------------------------------
// Kernel 1: WH = H @ W   (8192x128 @ 128x64)
// ---------------------------------------------------------------------------
__global__ __launch_bounds__(256) void wh_kernel(const float* __restrict__ h,
                                                 const float* __restrict__ w) {
    __shared__ __align__(16) float sW[F_IN * F_OUTD];   // 32 KB
    __shared__ __align__(16) float sH[4 * F_IN];        // 2 KB
    int t = threadIdx.x;
    int i0 = blockIdx.x * 4;

    #pragma unroll
    for (int k = t; k < F_IN * F_OUTD; k += 256) sW[k] = w[k];
    #pragma unroll
    for (int k = t; k < 4 * F_IN; k += 256)
        sH[k] = h[(size_t)(i0 + (k >> 7)) * F_IN + (k & 127)];
    __syncthreads();

    int f = t & 63;
    int r = t >> 6;   // 0..3
    const float* hr = sH + r * F_IN;
    float acc = 0.f;
    #pragma unroll
    for (int k = 0; k < F_IN; k += 4) {
        float4 h4 = *(const float4*)&hr[k];
        acc = fmaf(h4.x, sW[(k + 0) * F_OUTD + f], acc);
        acc = fmaf(h4.y, sW[(k + 1) * F_OUTD + f], acc);
        acc = fmaf(h4.z, sW[(k + 2) * F_OUTD + f], acc);
        acc = fmaf(h4.w, sW[(k + 3) * F_OUTD + f], acc);
    }
    g_wh[(size_t)(i0 + r) * F_OUTD + f] = acc;
}

// ---------------------------------------------------------------------------
// Kernel 2: src[i] = wh_i . a1 + edge_i * (w_edge . a3) ;  dst[i] = wh_i . a2
// att layout: a1 = att[0:64], a2 = att[64:128], a3 = att[128:192]
// ---------------------------------------------------------------------------
__global__ __launch_bounds__(256) void srcdst_kernel(const float* __restrict__ edge,
                                                     const float* __restrict__ att,
                                                     const float* __restrict__ w_edge) {
    int warp = threadIdx.x >> 5;
    int lane = threadIdx.x & 31;
    int i = blockIdx.x * 8 + warp;
    const float* whr = g_wh + (size_t)i * F_OUTD;

    float wl = whr[lane], wh2 = whr[lane + 32];
    float s = wl * att[lane]      + wh2 * att[lane + 32];
    float d = wl * att[64 + lane] + wh2 * att[96 + lane];
    float c = w_edge[lane] * att[128 + lane] + w_edge[lane + 32] * att[160 + lane];
    #pragma unroll
    for (int o = 16; o; o >>= 1) {
        s += __shfl_xor_sync(0xffffffffu, s, o);
        d += __shfl_xor_sync(0xffffffffu, d, o);
        c += __shfl_xor_sync(0xffffffffu, c, o);
    }
    if (lane == 0) {
        g_src[i] = s + edge[i] * c;
        g_dst[i] = d;
    }
}

// ---------------------------------------------------------------------------
// Kernel 3: fused masked-softmax aggregation + ELU.
//   For row tile [i0, i0+32): stream 128-wide column tiles.
//   Phase 1: w[r][j] = adj ? exp(leaky_relu(src_r + dst_j)) : 0   (no max-sub:
//            e is bounded ~[-2, 8], exp fits fp32 comfortably)
//   Phase 2: num[r][f] += w[r][j] * wh[j][f] via packed fma.rn.f32x2,
//            Z[r] += w[r][j].
//   Epilogue: out = elu(num / Z).
//
// Shared (static, exactly 48 KB):
//   sWh: [128][64] floats, f-contiguous                    (32 KB, at sm+0)
//   sW : [32][128] floats, column-swizzled (j+r)&127       (16 KB, at sm+8192)
//   reduction buffers overlay sWh after the tile loop.
// ---------------------------------------------------------------------------
__device__ __forceinline__ void ffma2(unsigned long long& d,
                                      unsigned long long a,
                                      unsigned long long b) {
    asm("fma.rn.f32x2 %0, %1, %2, %0;" : "+l"(d) : "l"(a), "l"(b));
}
__device__ __forceinline__ unsigned long long dup_f32(float w) {
    unsigned long long r;
    asm("mov.b64 %0, {%1, %1};" : "=l"(r) : "f"(w));
    return r;
}

__global__ void __launch_bounds__(256, 2) attn_kernel(const int* __restrict__ adj,
                                                      float* __restrict__ out) {
    __shared__ __align__(16) float sm[12288];   // 48 KB
    float* sWh = sm;            // 8192 floats
    float* sW  = sm + 8192;     // 4096 floats

    int t    = threadIdx.x;
    int i0   = blockIdx.x * BI;
    int warp = t >> 5, lane = t & 31;
    int rq   = lane >> 3;       // row quad 0..3 (rows rq*8 .. rq*8+7)
    int fg   = lane & 7;        // feature group (features fg*8 .. fg*8+7)
    int jj1  = t & 127;         // phase-1 column
    int rb1  = (t >> 7) * 16;   // phase-1 row base (0 or 16)

    unsigned long long acc[8][4];
    #pragma unroll
    for (int m = 0; m < 8; m++)
        #pragma unroll
        for (int p = 0; p < 4; p++) acc[m][p] = 0ull;
    float zacc[8] = {0.f, 0.f, 0.f, 0.f, 0.f, 0.f, 0.f, 0.f};

    for (int jt = 0; jt < N_NODES; jt += BJ) {
        __syncthreads();   // previous phase-2 reads done before overwrite

        // load wh tile [128][64] (2048 float4, 8 per thread, coalesced)
        {
            float4* d4 = (float4*)sWh;
            const float4* s4 = (const float4*)(g_wh + (size_t)jt * F_OUTD);
            #pragma unroll
            for (int k = 0; k < 8; k++) d4[t + k * 256] = s4[t + k * 256];
        }

        // phase 1: attention weights into sW (swizzled, conflict-free)
        {
            float d = g_dst[jt + jj1];
            const int* ap = adj + (size_t)(i0 + rb1) * N_NODES + jt + jj1;
            #pragma unroll
            for (int m = 0; m < 16; m++) {
                int r = rb1 + m;
                int a = ap[(size_t)m * N_NODES];          // coalesced 128B/warp
                float e = g_src[i0 + r] + d;              // broadcast L1 hit
                e = (e > 0.f) ? e : ALPHA * e;
                float w = (a > 0) ? __expf(e) : 0.f;
                sW[r * 128 + ((jj1 + r) & 127)] = w;
            }
        }
        __syncthreads();

        // phase 2: packed-f32x2 accumulation. Warp handles 16 j's.
        int jbase = warp * 16;
        #pragma unroll 2
        for (int jx = 0; jx < 16; jx++) {
            int jj = jbase + jx;
            const float* whp = sWh + jj * F_OUTD + fg * 8;
            ulonglong2 q0 = *(const ulonglong2*)(whp);       // features 0..3 (packed pairs)
            ulonglong2 q1 = *(const ulonglong2*)(whp + 4);   // features 4..7
            unsigned long long whv0 = q0.x, whv1 = q0.y, whv2 = q1.x, whv3 = q1.y;
            #pragma unroll
            for (int m = 0; m < 8; m++) {
                int r = rq * 8 + m;
                float w = sW[r * 128 + ((jj + r) & 127)];    // 4 addrs x 8-way bcast
                zacc[m] += w;
                unsigned long long w2 = dup_f32(w);
                ffma2(acc[m][0], w2, whv0);
                ffma2(acc[m][1], w2, whv1);
                ffma2(acc[m][2], w2, whv2);
                ffma2(acc[m][3], w2, whv3);
            }
        }
    }

    // cross-warp reduction: overlay sRed[32][64] + sZ[32] onto sWh region
    __syncthreads();
    float* sRed = sm;           // 2048 floats
    float* sZ   = sm + 2048;    // 32 floats
    for (int wsel = 0; wsel < 8; ++wsel) {
        if (warp == wsel) {
            #pragma unroll
            for (int m = 0; m < 8; m++) {
                int r = rq * 8 + m;
                float* rp = sRed + r * F_OUTD + fg * 8;
                #pragma unroll
                for (int p = 0; p < 4; p++) {
                    float lo, hi;
                    asm("mov.b64 {%0, %1}, %2;" : "=f"(lo), "=f"(hi) : "l"(acc[m][p]));
                    if (wsel == 0) { rp[2 * p] = lo;  rp[2 * p + 1] = hi; }
                    else           { rp[2 * p] += lo; rp[2 * p + 1] += hi; }
                }
                if (fg == 0) {
                    if (wsel == 0) sZ[r] = zacc[m];
                    else           sZ[r] += zacc[m];
                }
            }
        }
        __syncthreads();
    }

    // epilogue: out = elu(num / Z)
    #pragma unroll
    for (int k = 0; k < 8; k++) {
        int idx = t + k * 256;
        int r = idx >> 6;
        float v = sRed[idx] / sZ[r];
        v = (v > 0.f) ? v : expm1f(v);
        out[(size_t)i0 * F_OUTD + idx] = v;
    }
}

// ---------------------------------------------------------------------------
// Launch. Inputs (metadata order): 0 h_nodes(8192x128 f32), 1 edge(8192x1 f32),
// 2 adj(8192x8192 i32), 3 weight(128x64 f32), 4 att(192x1 f32), 5 w_edge(1x64 f32)
// Output: 8192x64 f32
// ---------------------------------------------------------------------------
extern "C" void kernel_launch(void* const* d_in, const int* in_sizes, int n_in,
                              void* d_out, int out_size) {
    const float* h      = (const float*)d_in[0];
    const float* edge   = (const float*)d_in[1];
    const int*   adj    = (const int*)d_in[2];
    const float* weight = (const float*)d_in[3];
    const float* att    = (const float*)d_in[4];
    const float* w_edge = (const float*)d_in[5];
    float* out = (float*)d_out;

    wh_kernel<<<N_NODES / 4, 256>>>(h, weight);
    srcdst_kernel<<<N_NODES / 8, 256>>>(edge, att, w_edge);
    attn_kernel<<<N_NODES / BI, 256>>>(adj, out);
}

// round 6
// speedup vs baseline: 3.6508x; 3.6508x over previous
#include <cuda_runtime.h>
#include <cuda_fp16.h>
#include <cstdint>

#define NN     8192
#define F_IN   128
#define F_OUTD 64
#define ALPHA  0.2f
#define L2E    1.4426950408889634f
#define ESHIFT 5.7707801635558537f   // 4 * log2(e): w = 2^(leaky*L2E - ESHIFT)

// ---------------------------------------------------------------------------
// Device scratch (allocations forbidden -> __device__ globals)
// ---------------------------------------------------------------------------
__device__ float  g_wh[NN * F_OUTD];
__device__ __half g_whT16[F_OUTD * NN];     // [f][i] fp16 transpose of wh
__device__ float  g_src[NN];
__device__ float  g_dst[NN];
__device__ float  g_part[128 * 128 * 66];   // [cta][row][64 num, 1 Z, pad]

// ---------------------------------------------------------------------------
// Kernel 1: WH = H @ W (fp32) + fp16 transpose WH^T. 32 rows per block.
// ---------------------------------------------------------------------------
__global__ __launch_bounds__(256) void wh_kernel(const float* __restrict__ h,
                                                 const float* __restrict__ w) {
    __shared__ __align__(16) float sW[F_IN * F_OUTD];  // 32 KB
    __shared__ __align__(16) float sH[32 * F_IN];      // 16 KB (reused as sT)
    int t = threadIdx.x;
    int i0 = blockIdx.x * 32;

    {
        float4* dw = (float4*)sW;
        const float4* swg = (const float4*)w;
        #pragma unroll
        for (int k = 0; k < 8; k++) dw[t + k * 256] = swg[t + k * 256];
        float4* dh = (float4*)sH;
        const float4* shg = (const float4*)(h + (size_t)i0 * F_IN);
        #pragma unroll
        for (int k = 0; k < 4; k++) dh[t + k * 256] = shg[t + k * 256];
    }
    __syncthreads();

    int f = t & 63;
    int rg = t >> 6;  // 0..3 -> rows rg*8 .. rg*8+7
    float acc[8] = {0.f, 0.f, 0.f, 0.f, 0.f, 0.f, 0.f, 0.f};
    #pragma unroll 4
    for (int k = 0; k < F_IN; k += 4) {
        float w0 = sW[(k + 0) * F_OUTD + f];
        float w1 = sW[(k + 1) * F_OUTD + f];
        float w2 = sW[(k + 2) * F_OUTD + f];
        float w3 = sW[(k + 3) * F_OUTD + f];
        #pragma unroll
        for (int m = 0; m < 8; m++) {
            float4 h4 = *(const float4*)&sH[(rg * 8 + m) * F_IN + k];
            acc[m] = fmaf(h4.x, w0, acc[m]);
            acc[m] = fmaf(h4.y, w1, acc[m]);
            acc[m] = fmaf(h4.z, w2, acc[m]);
            acc[m] = fmaf(h4.w, w3, acc[m]);
        }
    }
    #pragma unroll
    for (int m = 0; m < 8; m++)
        g_wh[(size_t)(i0 + rg * 8 + m) * F_OUTD + f] = acc[m];

    // fp16 transpose staging (reuse sH)
    __syncthreads();
    __half* sT = (__half*)sH;   // [64 f][32 r]
    #pragma unroll
    for (int m = 0; m < 8; m++)
        sT[f * 32 + rg * 8 + m] = __float2half_rn(acc[m]);
    __syncthreads();
    {
        int f2 = t >> 2, seg = t & 3;
        uint4 v = *(const uint4*)(sT + f2 * 32 + seg * 8);
        *(uint4*)(g_whT16 + (size_t)f2 * NN + i0 + seg * 8) = v;
    }
}

// ---------------------------------------------------------------------------
// Kernel 2: src / dst vectors
// ---------------------------------------------------------------------------
__global__ __launch_bounds__(256) void srcdst_kernel(const float* __restrict__ edge,
                                                     const float* __restrict__ att,
                                                     const float* __restrict__ w_edge) {
    int warp = threadIdx.x >> 5;
    int lane = threadIdx.x & 31;
    int i = blockIdx.x * 8 + warp;
    const float* whr = g_wh + (size_t)i * F_OUTD;

    float wl = whr[lane], wh2 = whr[lane + 32];
    float s = wl * att[lane]      + wh2 * att[lane + 32];
    float d = wl * att[64 + lane] + wh2 * att[96 + lane];
    float c = w_edge[lane] * att[128 + lane] + w_edge[lane + 32] * att[160 + lane];
    #pragma unroll
    for (int o = 16; o; o >>= 1) {
        s += __shfl_xor_sync(0xffffffffu, s, o);
        d += __shfl_xor_sync(0xffffffffu, d, o);
        c += __shfl_xor_sync(0xffffffffu, c, o);
    }
    if (lane == 0) {
        g_src[i] = s + edge[i] * c;
        g_dst[i] = d;
    }
}

// ---------------------------------------------------------------------------
// mma.sync / ldmatrix helpers (arch-agnostic HMMA path; tcgen05 rejected by
// the harness's non-'a' ptxas target)
// ---------------------------------------------------------------------------
__device__ __forceinline__ uint32_t smem_u32(const void* p) {
    uint32_t a;
    asm("{ .reg .u64 t; cvta.to.shared.u64 t, %1; cvt.u32.u64 %0, t; }"
        : "=r"(a) : "l"(p));
    return a;
}
__device__ __forceinline__ void mma16816(float* c, uint32_t a0, uint32_t a1,
                                         uint32_t a2, uint32_t a3,
                                         uint32_t b0, uint32_t b1) {
    asm volatile(
        "mma.sync.aligned.m16n8k16.row.col.f32.f16.f16.f32 "
        "{%0,%1,%2,%3}, {%4,%5,%6,%7}, {%8,%9}, {%0,%1,%2,%3};"
        : "+f"(c[0]), "+f"(c[1]), "+f"(c[2]), "+f"(c[3])
        : "r"(a0), "r"(a1), "r"(a2), "r"(a3), "r"(b0), "r"(b1));
}
__device__ __forceinline__ void ldsm_x4(uint32_t* r, uint32_t addr) {
    asm volatile("ldmatrix.sync.aligned.m8n8.x4.shared.b16 {%0,%1,%2,%3}, [%4];"
                 : "=r"(r[0]), "=r"(r[1]), "=r"(r[2]), "=r"(r[3]) : "r"(addr));
}
// two packed fp16 attention weights for one row, one (c, c+1) column pair
__device__ __forceinline__ uint32_t wpair(float s, float2 d, int2 a) {
    float e0 = s + d.x, e1 = s + d.y;
    float l0 = fmaxf(e0, ALPHA * e0);           // leaky_relu (alpha < 1)
    float l1 = fmaxf(e1, ALPHA * e1);
    float g0 = a.x ? fmaf(l0, L2E, -ESHIFT) : -30.f;  // 2^-30 -> fp16 0
    float g1 = a.y ? fmaf(l1, L2E, -ESHIFT) : -30.f;
    uint32_t p;
    asm("cvt.rn.f16x2.f32 %0, %1, %2;" : "=r"(p) : "f"(g1), "f"(g0));  // hi,lo
    asm("ex2.approx.f16x2 %0, %0;" : "+r"(p));
    return p;
}

// ---------------------------------------------------------------------------
// Kernel 3: HMMA masked-softmax aggregation.
// CTA bx: rows [128*(bx>>1), +128), j range [(bx&1)*4096, +4096), 32 tiles.
// A-frags computed in registers (adj int2, ex2.f16x2); B = WH^T tile in
// double-buffered swizzled shared via ldmatrix; Z via all-ones-B MMA.
// ---------------------------------------------------------------------------
__global__ void __launch_bounds__(256, 1) attn_kernel(const int* __restrict__ adj) {
    __shared__ __align__(1024) __half sB[2][64 * 128];   // 2 x 16 KB

    int t = threadIdx.x, lane = t & 31, w = t >> 5;
    int bx = blockIdx.x;
    int i0 = (bx >> 1) * 128, j0 = (bx & 1) * 4096;

    int l4 = lane & 3;         // column-pair selector
    int lr = lane >> 2;        // row-in-8
    int row0 = w * 16 + lr;    // second row = row0 + 8

    float acc[8][4];           // 8 n-tiles (f = p*8 + ...)
    float zc[4];
    #pragma unroll
    for (int p = 0; p < 8; p++)
        #pragma unroll
        for (int q = 0; q < 4; q++) acc[p][q] = 0.f;
    #pragma unroll
    for (int q = 0; q < 4; q++) zc[q] = 0.f;

    float src0 = g_src[i0 + row0];
    float src1 = g_src[i0 + row0 + 8];
    const int* arow = adj + (size_t)(i0 + row0) * NN + j0 + l4 * 2;

    // B-copy indices: thread covers f = t>>2, 4 x 16B chunks
    int fB = t >> 2, qb = (t & 3) * 4;
    const uint4* bsrc_base = (const uint4*)(g_whT16 + (size_t)fB * NN + j0);
    // ldmatrix per-lane geometry
    int fo  = (lane & 7) + ((lane & 16) >> 1);   // f offset within n-tile pair
    int cb  = (lane >> 3) & 1;                   // k-half selector
    int sw7 = lane & 7;                          // swizzle XOR (== f & 7)
    uint32_t sb_base = smem_u32(sB);

    // prologue: fill buffer 0
    #pragma unroll
    for (int q = 0; q < 4; q++) {
        uint4 v = bsrc_base[qb + q];
        *(uint4*)((char*)(sB[0] + fB * 128) + (((qb + q) ^ (fB & 7)) << 4)) = v;
    }
    __syncthreads();

    const uint32_t ONES = 0x3C003C00u;  // fp16 {1,1}

    for (int lt = 0; lt < 32; lt++) {
        int s = lt & 1;
        int jc = j0 + lt * 128;

        // prefetch next B tile into the other buffer (loads issue early)
        if (lt < 31) {
            const uint4* bs = (const uint4*)((const __half*)bsrc_base + (lt + 1) * 128);
            #pragma unroll
            for (int q = 0; q < 4; q++) {
                uint4 v = bs[qb + q];
                *(uint4*)((char*)(sB[s ^ 1] + fB * 128) +
                          (((qb + q) ^ (fB & 7)) << 4)) = v;
            }
        }

        const int*   ap = arow + lt * 128;
        const float* dp = g_dst + jc + l4 * 2;
        uint32_t lmbase = sb_base + (uint32_t)s * 16384u + (uint32_t)fo * 256u;

        #pragma unroll
        for (int ks = 0; ks < 8; ks++) {
            // adjacency (int2, 100% sector utilization) + dst
            int2 a00 = *(const int2*)(ap + ks * 16);
            int2 a01 = *(const int2*)(ap + ks * 16 + 8);
            int2 a10 = *(const int2*)(ap + ks * 16 + 8 * NN);
            int2 a11 = *(const int2*)(ap + ks * 16 + 8 * NN + 8);
            float2 d0 = *(const float2*)(dp + ks * 16);
            float2 d1 = *(const float2*)(dp + ks * 16 + 8);

            // A fragment (m16n8k16 layout, packed fp16 pairs)
            uint32_t fa0 = wpair(src0, d0, a00);   // rows 0-7,  k low
            uint32_t fa1 = wpair(src1, d0, a10);   // rows 8-15, k low
            uint32_t fa2 = wpair(src0, d1, a01);   // rows 0-7,  k+8
            uint32_t fa3 = wpair(src1, d1, a11);   // rows 8-15, k+8

            // B fragments for all 8 n-tiles (4x ldmatrix.x4)
            uint32_t chx = (uint32_t)(((2 * ks + cb) ^ sw7) << 4);
            uint32_t b[16];
            #pragma unroll
            for (int pp = 0; pp < 4; pp++) {
                ldsm_x4(b + pp * 4, lmbase + (uint32_t)(pp * 4096) + chx);
            }
            // 8 numerator MMAs + 1 Z MMA
            #pragma unroll
            for (int p = 0; p < 8; p++)
                mma16816(acc[p], fa0, fa1, fa2, fa3, b[p * 2], b[p * 2 + 1]);
            mma16816(zc, fa0, fa1, fa2, fa3, ONES, ONES);
        }
        __syncthreads();
    }

    // epilogue: C frags -> g_part (stride 66, aligned float2)
    size_t rbase = (size_t)bx * 128 + row0;
    #pragma unroll
    for (int p = 0; p < 8; p++) {
        float* o0 = g_part + rbase * 66 + p * 8 + l4 * 2;
        float* o1 = o0 + 8 * 66;
        *(float2*)o0 = make_float2(acc[p][0], acc[p][1]);
        *(float2*)o1 = make_float2(acc[p][2], acc[p][3]);
    }
    if (l4 == 0) {
        g_part[rbase * 66 + 64] = zc[0];
        g_part[(rbase + 8) * 66 + 64] = zc[2];
    }
}

// ---------------------------------------------------------------------------
// Kernel 4: combine halves, normalize, ELU
// ---------------------------------------------------------------------------
__global__ __launch_bounds__(256) void combine_kernel(float* __restrict__ out) {
    int idx = blockIdx.x * 256 + threadIdx.x;   // 0 .. 8192*64-1
    int i = idx >> 6, f = idx & 63;
    int b0 = (i >> 7) * 2, r = i & 127;
    const float* p0 = g_part + (size_t)(b0 * 128 + r) * 66;
    const float* p1 = p0 + 128 * 66;
    float n = p0[f] + p1[f];
    float z = p0[64] + p1[64];
    float v = n / z;
    out[idx] = (v > 0.f) ? v : expm1f(v);
}

// ---------------------------------------------------------------------------
// Launch. Inputs: 0 h_nodes(8192x128 f32), 1 edge(8192 f32), 2 adj(8192^2 i32),
//                 3 weight(128x64 f32), 4 att(192 f32), 5 w_edge(64 f32)
// ---------------------------------------------------------------------------
extern "C" void kernel_launch(void* const* d_in, const int* in_sizes, int n_in,
                              void* d_out, int out_size) {
    const float* h      = (const float*)d_in[0];
    const float* edge   = (const float*)d_in[1];
    const int*   adj    = (const int*)d_in[2];
    const float* weight = (const float*)d_in[3];
    const float* att    = (const float*)d_in[4];
    const float* w_edge = (const float*)d_in[5];
    float* out = (float*)d_out;

    wh_kernel<<<NN / 32, 256>>>(h, weight);
    srcdst_kernel<<<NN / 8, 256>>>(edge, att, w_edge);
    attn_kernel<<<128, 256>>>(adj);
    combine_kernel<<<NN * F_OUTD / 256, 256>>>(out);
}

// round 7
// speedup vs baseline: 4.5904x; 1.2574x over previous
#include <cuda_runtime.h>
#include <cuda_fp16.h>
#include <cstdint>

#define NN     8192
#define F_IN   128
#define F_OUTD 64
#define ALPHA  0.2f
#define L2E    1.4426950408889634f
#define ESHIFT 5.7707801635558537f   // 4 * log2(e): w = 2^(leaky*L2E - ESHIFT)

// ---------------------------------------------------------------------------
// Device scratch (allocations forbidden -> __device__ globals)
// ---------------------------------------------------------------------------
__device__ float  g_wh[NN * F_OUTD];
__device__ __half g_whT16[F_OUTD * NN];     // [f][i] fp16 transpose of wh
__device__ float  g_src[NN];
__device__ float  g_dst[NN];
__device__ float  g_part[256 * 128 * 66];   // [cta][row][64 num, 1 Z, pad]

// ---------------------------------------------------------------------------
// Kernel 1: WH = H @ W (fp32) + fp16 transpose WH^T. 32 rows per block.
// ---------------------------------------------------------------------------
__global__ __launch_bounds__(256) void wh_kernel(const float* __restrict__ h,
                                                 const float* __restrict__ w) {
    __shared__ __align__(16) float sW[F_IN * F_OUTD];  // 32 KB
    __shared__ __align__(16) float sH[32 * F_IN];      // 16 KB (reused as sT)
    int t = threadIdx.x;
    int i0 = blockIdx.x * 32;

    {
        float4* dw = (float4*)sW;
        const float4* swg = (const float4*)w;
        #pragma unroll
        for (int k = 0; k < 8; k++) dw[t + k * 256] = swg[t + k * 256];
        float4* dh = (float4*)sH;
        const float4* shg = (const float4*)(h + (size_t)i0 * F_IN);
        #pragma unroll
        for (int k = 0; k < 4; k++) dh[t + k * 256] = shg[t + k * 256];
    }
    __syncthreads();

    int f = t & 63;
    int rg = t >> 6;  // 0..3 -> rows rg*8 .. rg*8+7
    float acc[8] = {0.f, 0.f, 0.f, 0.f, 0.f, 0.f, 0.f, 0.f};
    #pragma unroll 4
    for (int k = 0; k < F_IN; k += 4) {
        float w0 = sW[(k + 0) * F_OUTD + f];
        float w1 = sW[(k + 1) * F_OUTD + f];
        float w2 = sW[(k + 2) * F_OUTD + f];
        float w3 = sW[(k + 3) * F_OUTD + f];
        #pragma unroll
        for (int m = 0; m < 8; m++) {
            float4 h4 = *(const float4*)&sH[(rg * 8 + m) * F_IN + k];
            acc[m] = fmaf(h4.x, w0, acc[m]);
            acc[m] = fmaf(h4.y, w1, acc[m]);
            acc[m] = fmaf(h4.z, w2, acc[m]);
            acc[m] = fmaf(h4.w, w3, acc[m]);
        }
    }
    #pragma unroll
    for (int m = 0; m < 8; m++)
        g_wh[(size_t)(i0 + rg * 8 + m) * F_OUTD + f] = acc[m];

    // fp16 transpose staging (reuse sH)
    __syncthreads();
    __half* sT = (__half*)sH;   // [64 f][32 r]
    #pragma unroll
    for (int m = 0; m < 8; m++)
        sT[f * 32 + rg * 8 + m] = __float2half_rn(acc[m]);
    __syncthreads();
    {
        int f2 = t >> 2, seg = t & 3;
        uint4 v = *(const uint4*)(sT + f2 * 32 + seg * 8);
        *(uint4*)(g_whT16 + (size_t)f2 * NN + i0 + seg * 8) = v;
    }
}

// ---------------------------------------------------------------------------
// Kernel 2: src / dst vectors
// ---------------------------------------------------------------------------
__global__ __launch_bounds__(256) void srcdst_kernel(const float* __restrict__ edge,
                                                     const float* __restrict__ att,
                                                     const float* __restrict__ w_edge) {
    int warp = threadIdx.x >> 5;
    int lane = threadIdx.x & 31;
    int i = blockIdx.x * 8 + warp;
    const float* whr = g_wh + (size_t)i * F_OUTD;

    float wl = whr[lane], wh2 = whr[lane + 32];
    float s = wl * att[lane]      + wh2 * att[lane + 32];
    float d = wl * att[64 + lane] + wh2 * att[96 + lane];
    float c = w_edge[lane] * att[128 + lane] + w_edge[lane + 32] * att[160 + lane];
    #pragma unroll
    for (int o = 16; o; o >>= 1) {
        s += __shfl_xor_sync(0xffffffffu, s, o);
        d += __shfl_xor_sync(0xffffffffu, d, o);
        c += __shfl_xor_sync(0xffffffffu, c, o);
    }
    if (lane == 0) {
        g_src[i] = s + edge[i] * c;
        g_dst[i] = d;
    }
}

// ---------------------------------------------------------------------------
// mma.sync / ldmatrix helpers
// ---------------------------------------------------------------------------
__device__ __forceinline__ uint32_t smem_u32(const void* p) {
    uint32_t a;
    asm("{ .reg .u64 t; cvta.to.shared.u64 t, %1; cvt.u32.u64 %0, t; }"
        : "=r"(a) : "l"(p));
    return a;
}
__device__ __forceinline__ void mma16816(float* c, uint32_t a0, uint32_t a1,
                                         uint32_t a2, uint32_t a3,
                                         uint32_t b0, uint32_t b1) {
    asm volatile(
        "mma.sync.aligned.m16n8k16.row.col.f32.f16.f16.f32 "
        "{%0,%1,%2,%3}, {%4,%5,%6,%7}, {%8,%9}, {%0,%1,%2,%3};"
        : "+f"(c[0]), "+f"(c[1]), "+f"(c[2]), "+f"(c[3])
        : "r"(a0), "r"(a1), "r"(a2), "r"(a3), "r"(b0), "r"(b1));
}
__device__ __forceinline__ void ldsm_x4(uint32_t* r, uint32_t addr) {
    asm volatile("ldmatrix.sync.aligned.m8n8.x4.shared.b16 {%0,%1,%2,%3}, [%4];"
                 : "=r"(r[0]), "=r"(r[1]), "=r"(r[2]), "=r"(r[3]) : "r"(addr));
}
// two packed fp16 attention weights for one row, one (c, c+1) column pair
__device__ __forceinline__ uint32_t wpair(float s, float2 d, int2 a) {
    float e0 = s + d.x, e1 = s + d.y;
    float l0 = fmaxf(e0, ALPHA * e0);           // leaky_relu (alpha < 1)
    float l1 = fmaxf(e1, ALPHA * e1);
    float g0 = a.x ? fmaf(l0, L2E, -ESHIFT) : -30.f;  // 2^-30 -> fp16 0
    float g1 = a.y ? fmaf(l1, L2E, -ESHIFT) : -30.f;
    uint32_t p;
    asm("cvt.rn.f16x2.f32 %0, %1, %2;" : "=r"(p) : "f"(g1), "f"(g0));  // hi,lo
    asm("ex2.approx.f16x2 %0, %0;" : "+r"(p));
    return p;
}

// ---------------------------------------------------------------------------
// Kernel 3: HMMA masked-softmax aggregation.
// Grid 256 = 64 row-blocks x 4 j-quarters; 2 CTAs/SM (16 warps) for latency
// hiding. CTA: rows [128*(bx>>2), +128), j [(bx&3)*2048, +2048), 16 K=128
// tiles. A-frags in registers (adj int2 -> ex2.f16x2), B via ldmatrix from
// double-buffered swizzled smem, Z via all-ones-B MMA. Adj/dst loads software-
// pipelined one k-step ahead.
// ---------------------------------------------------------------------------
__global__ void __launch_bounds__(256, 2) attn_kernel(const int* __restrict__ adj) {
    __shared__ __align__(1024) __half sB[2][64 * 128];   // 2 x 16 KB

    int t = threadIdx.x, lane = t & 31, w = t >> 5;
    int bx = blockIdx.x;
    int i0 = (bx >> 2) * 128, j0 = (bx & 3) * 2048;

    int l4 = lane & 3;         // column-pair selector
    int lr = lane >> 2;        // row-in-8
    int row0 = w * 16 + lr;    // second row = row0 + 8

    float acc[8][4];           // 8 n-tiles
    float zc[4];
    #pragma unroll
    for (int p = 0; p < 8; p++)
        #pragma unroll
        for (int q = 0; q < 4; q++) acc[p][q] = 0.f;
    #pragma unroll
    for (int q = 0; q < 4; q++) zc[q] = 0.f;

    float src0 = g_src[i0 + row0];
    float src1 = g_src[i0 + row0 + 8];
    const int* arow = adj + (size_t)(i0 + row0) * NN + j0 + l4 * 2;

    // B-copy indices: thread covers f = t>>2, 4 x 16B chunks
    int fB = t >> 2, qb = (t & 3) * 4;
    const uint4* bsrc_base = (const uint4*)(g_whT16 + (size_t)fB * NN + j0);
    // ldmatrix per-lane geometry
    int fo  = (lane & 7) + ((lane & 16) >> 1);
    int cb  = (lane >> 3) & 1;
    int sw7 = lane & 7;
    uint32_t sb_base = smem_u32(sB);

    // prologue: fill buffer 0
    #pragma unroll
    for (int q = 0; q < 4; q++) {
        uint4 v = bsrc_base[qb + q];
        *(uint4*)((char*)(sB[0] + fB * 128) + (((qb + q) ^ (fB & 7)) << 4)) = v;
    }
    __syncthreads();

    const uint32_t ONES = 0x3C003C00u;  // fp16 {1,1}

    for (int lt = 0; lt < 16; lt++) {
        int s = lt & 1;
        int jc = j0 + lt * 128;

        // prefetch next B tile into the other buffer
        if (lt < 15) {
            const uint4* bs = (const uint4*)((const __half*)bsrc_base + (lt + 1) * 128);
            #pragma unroll
            for (int q = 0; q < 4; q++) {
                uint4 v = bs[qb + q];
                *(uint4*)((char*)(sB[s ^ 1] + fB * 128) +
                          (((qb + q) ^ (fB & 7)) << 4)) = v;
            }
        }

        const int*   ap = arow + lt * 128;
        const float* dp = g_dst + jc + l4 * 2;
        uint32_t lmbase = sb_base + (uint32_t)s * 16384u + (uint32_t)fo * 256u;

        // software-pipelined adjacency/dst: preload k-step 0
        int2 a00 = *(const int2*)(ap);
        int2 a01 = *(const int2*)(ap + 8);
        int2 a10 = *(const int2*)(ap + 8 * NN);
        int2 a11 = *(const int2*)(ap + 8 * NN + 8);
        float2 d0 = *(const float2*)(dp);
        float2 d1 = *(const float2*)(dp + 8);

        #pragma unroll
        for (int ks = 0; ks < 8; ks++) {
            int2 c00 = a00, c01 = a01, c10 = a10, c11 = a11;
            float2 e0 = d0, e1 = d1;
            if (ks < 7) {   // issue next step's loads before this step's math
                a00 = *(const int2*)(ap + (ks + 1) * 16);
                a01 = *(const int2*)(ap + (ks + 1) * 16 + 8);
                a10 = *(const int2*)(ap + (ks + 1) * 16 + 8 * NN);
                a11 = *(const int2*)(ap + (ks + 1) * 16 + 8 * NN + 8);
                d0  = *(const float2*)(dp + (ks + 1) * 16);
                d1  = *(const float2*)(dp + (ks + 1) * 16 + 8);
            }

            uint32_t fa0 = wpair(src0, e0, c00);   // rows 0-7,  k low
            uint32_t fa1 = wpair(src1, e0, c10);   // rows 8-15, k low
            uint32_t fa2 = wpair(src0, e1, c01);   // rows 0-7,  k+8
            uint32_t fa3 = wpair(src1, e1, c11);   // rows 8-15, k+8

            uint32_t chx = (uint32_t)(((2 * ks + cb) ^ sw7) << 4);
            uint32_t b[16];
            #pragma unroll
            for (int pp = 0; pp < 4; pp++)
                ldsm_x4(b + pp * 4, lmbase + (uint32_t)(pp * 4096) + chx);

            #pragma unroll
            for (int p = 0; p < 8; p++)
                mma16816(acc[p], fa0, fa1, fa2, fa3, b[p * 2], b[p * 2 + 1]);
            mma16816(zc, fa0, fa1, fa2, fa3, ONES, ONES);
        }
        __syncthreads();
    }

    // epilogue: C frags -> g_part (stride 66, aligned float2)
    size_t rbase = (size_t)bx * 128 + row0;
    #pragma unroll
    for (int p = 0; p < 8; p++) {
        float* o0 = g_part + rbase * 66 + p * 8 + l4 * 2;
        float* o1 = o0 + 8 * 66;
        *(float2*)o0 = make_float2(acc[p][0], acc[p][1]);
        *(float2*)o1 = make_float2(acc[p][2], acc[p][3]);
    }
    if (l4 == 0) {
        g_part[rbase * 66 + 64] = zc[0];
        g_part[(rbase + 8) * 66 + 64] = zc[2];
    }
}

// ---------------------------------------------------------------------------
// Kernel 4: combine 4 j-quarter partials, normalize, ELU
// ---------------------------------------------------------------------------
__global__ __launch_bounds__(256) void combine_kernel(float* __restrict__ out) {
    int idx = blockIdx.x * 256 + threadIdx.x;   // 0 .. 8192*64-1
    int i = idx >> 6, f = idx & 63;
    int b0 = (i >> 7) * 4, r = i & 127;
    const float* p = g_part + (size_t)(b0 * 128 + r) * 66;
    float n = 0.f, z = 0.f;
    #pragma unroll
    for (int q = 0; q < 4; q++) {
        n += p[(size_t)q * 128 * 66 + f];
        z += p[(size_t)q * 128 * 66 + 64];
    }
    float v = n / z;
    out[idx] = (v > 0.f) ? v : expm1f(v);
}

// ---------------------------------------------------------------------------
// Launch. Inputs: 0 h_nodes(8192x128 f32), 1 edge(8192 f32), 2 adj(8192^2 i32),
//                 3 weight(128x64 f32), 4 att(192 f32), 5 w_edge(64 f32)
// ---------------------------------------------------------------------------
extern "C" void kernel_launch(void* const* d_in, const int* in_sizes, int n_in,
                              void* d_out, int out_size) {
    const float* h      = (const float*)d_in[0];
    const float* edge   = (const float*)d_in[1];
    const int*   adj    = (const int*)d_in[2];
    const float* weight = (const float*)d_in[3];
    const float* att    = (const float*)d_in[4];
    const float* w_edge = (const float*)d_in[5];
    float* out = (float*)d_out;

    wh_kernel<<<NN / 32, 256>>>(h, weight);
    srcdst_kernel<<<NN / 8, 256>>>(edge, att, w_edge);
    attn_kernel<<<256, 256>>>(adj);
    combine_kernel<<<NN * F_OUTD / 256, 256>>>(out);
}